// round 1
// baseline (speedup 1.0000x reference)
#include <cuda_runtime.h>

#define BB 8
#define DD 4096
#define HH 32
#define HDD 128
#define KVV 512
#define PASTN 8191
#define TOTALN 8192
#define SCALEF 0.08838834764831845f  // 128^-0.5

// ---------------- scratch (static device globals; no allocation) ----------------
__device__ float g_cnew[BB * KVV];                       // fresh compressed token per batch
__device__ float g_qpart[8 * BB * HH * KVV];             // k-split partials for q_abs
__device__ float g_qabs[BB * HH * KVV];                  // scaled absorbed queries
__device__ float g_scores[BB * HH * TOTALN];             // scores -> attn (in place)
__device__ float g_opart[16 * BB * HH * KVV];            // s-split partials for o_c
__device__ float g_oc[BB * HH * KVV];                    // attn @ c_full
__device__ float g_ohead[BB * HH * HDD];                 // per-head up-projected output

// packed dual-fp32 FMA (sm_100+): 2 fp32 FMAs per instruction
__device__ __forceinline__ float2 ffma2(const float2 a, const float2 b, const float2 c) {
    float2 d;
    asm("fma.rn.f32x2 %0, %1, %2, %3;"
        : "=l"(*(unsigned long long*)&d)
        : "l"(*(const unsigned long long*)&a),
          "l"(*(const unsigned long long*)&b),
          "l"(*(const unsigned long long*)&c));
    return d;
}

// ---------------- K0: zero d_out and g_cnew ----------------
__global__ void k_init(float* __restrict__ out) {
    int i = blockIdx.x * 256 + threadIdx.x;       // grid 128 -> 32768 threads
    out[i] = 0.f;
    if (i < BB * KVV) g_cnew[i] = 0.f;
}

// ---------------- K1: c_new[b] = x[b] @ w_compress  (k-split, atomic) ----------------
__global__ __launch_bounds__(256) void k_compress(const float* __restrict__ x,
                                                  const float* __restrict__ wc) {
    __shared__ float xs[BB * 128];
    int kc = blockIdx.x;          // 32 chunks of 128 k
    int tid = threadIdx.x;        // 256; owns n-pair tid*2
    for (int i = tid; i < BB * 128; i += 256)
        xs[i] = x[(i >> 7) * DD + kc * 128 + (i & 127)];
    __syncthreads();
    float2 acc[BB];
    #pragma unroll
    for (int b = 0; b < BB; b++) acc[b] = make_float2(0.f, 0.f);
    const float* wp = wc + (size_t)kc * 128 * KVV + tid * 2;
    #pragma unroll 4
    for (int k = 0; k < 128; k++) {
        float2 w2 = *(const float2*)(wp + (size_t)k * KVV);
        #pragma unroll
        for (int b = 0; b < BB; b++) {
            float xv = xs[b * 128 + k];
            acc[b] = ffma2(make_float2(xv, xv), w2, acc[b]);
        }
    }
    #pragma unroll
    for (int b = 0; b < BB; b++) {
        atomicAdd(&g_cnew[b * KVV + tid * 2 + 0], acc[b].x);
        atomicAdd(&g_cnew[b * KVV + tid * 2 + 1], acc[b].y);
    }
}

// ---------------- K2: q_abs partials  (scale folded into x) ----------------
// grid (kc=8, h=32); 256 threads; thread owns n-pair tid*2, all 8 batches
__global__ __launch_bounds__(256) void k_qabs(const float* __restrict__ x,
                                              const float* __restrict__ aqk) {
    __shared__ float2 xd[BB * 512];   // duplicated (v,v), pre-scaled
    int kc = blockIdx.x;
    int h  = blockIdx.y;
    int tid = threadIdx.x;
    for (int i = tid; i < BB * 512; i += 256) {
        float v = x[(i >> 9) * DD + kc * 512 + (i & 511)] * SCALEF;
        xd[i] = make_float2(v, v);
    }
    __syncthreads();
    float2 acc[BB];
    #pragma unroll
    for (int b = 0; b < BB; b++) acc[b] = make_float2(0.f, 0.f);
    const float* ap = aqk + ((size_t)h * DD + (size_t)kc * 512) * KVV + tid * 2;
    #pragma unroll 8
    for (int k = 0; k < 512; k++) {
        float2 a2 = *(const float2*)(ap + (size_t)k * KVV);
        #pragma unroll
        for (int b = 0; b < BB; b++)
            acc[b] = ffma2(a2, xd[b * 512 + k], acc[b]);
    }
    #pragma unroll
    for (int b = 0; b < BB; b++)
        *(float2*)&g_qpart[((size_t)(kc * BB + b) * HH + h) * KVV + tid * 2] = acc[b];
}

// reduce 8 k-partials -> g_qabs
__global__ void k_redq() {
    int i = blockIdx.x * 256 + threadIdx.x;   // grid 128 -> 32768 float4 columns
    const float4* p = (const float4*)g_qpart;
    float4 s = make_float4(0.f, 0.f, 0.f, 0.f);
    #pragma unroll
    for (int c = 0; c < 8; c++) {
        float4 t = p[c * 32768 + i];
        s.x += t.x; s.y += t.y; s.z += t.z; s.w += t.w;
    }
    ((float4*)g_qabs)[i] = s;
}

// ---------------- K3: scores[b,h,s] = q_abs[b,h,:] . c_full[b,s,:]  ----------------
// grid (st=32 s-tiles of 256, b=8); 128 threads; per-thread 8h x 4 s-pairs
__global__ __launch_bounds__(128) void k_scores(const float* __restrict__ past_c) {
    extern __shared__ float sm[];
    float* c_s = sm;                                   // [64 k][258] transposed, padded
    float2* qd = (float2*)(sm + 64 * 258);             // [32 h][64 k] duplicated
    int st = blockIdx.x, b = blockIdx.y;
    int tid = threadIdx.x;
    int w = tid >> 5, lane = tid & 31;
    int hg = w;          // h-octet per warp -> broadcast q loads
    int sg = lane;
    int s0 = st * 256;
    float2 acc[8][4];
    #pragma unroll
    for (int i = 0; i < 8; i++)
        #pragma unroll
        for (int j = 0; j < 4; j++) acc[i][j] = make_float2(0.f, 0.f);

    for (int kc = 0; kc < 8; kc++) {
        // load c chunk transposed: c_s[k][s]
        #pragma unroll
        for (int ss = 0; ss < 2; ss++) {
            int s = ss * 128 + w * 32 + lane;
            int sg_ = s0 + s;
            const float* row = (sg_ < PASTN) ? past_c + ((size_t)b * PASTN + sg_) * KVV
                                             : g_cnew + b * KVV;
            #pragma unroll
            for (int kq = 0; kq < 16; kq++) {
                float4 v = *(const float4*)(row + kc * 64 + kq * 4);
                c_s[(kq * 4 + 0) * 258 + s] = v.x;
                c_s[(kq * 4 + 1) * 258 + s] = v.y;
                c_s[(kq * 4 + 2) * 258 + s] = v.z;
                c_s[(kq * 4 + 3) * 258 + s] = v.w;
            }
        }
        for (int i = tid; i < 32 * 64; i += 128) {
            int hh = i >> 6, kk = i & 63;
            float q = g_qabs[((size_t)b * HH + hh) * KVV + kc * 64 + kk];
            qd[hh * 64 + kk] = make_float2(q, q);
        }
        __syncthreads();
        #pragma unroll 2
        for (int k = 0; k < 64; k++) {
            float2 q[8];
            #pragma unroll
            for (int i = 0; i < 8; i++) q[i] = qd[(hg * 8 + i) * 64 + k];
            #pragma unroll
            for (int j = 0; j < 4; j++) {
                float2 c2 = *(const float2*)&c_s[k * 258 + sg * 2 + j * 64];
                #pragma unroll
                for (int i = 0; i < 8; i++)
                    acc[i][j] = ffma2(q[i], c2, acc[i][j]);
            }
        }
        __syncthreads();
    }
    #pragma unroll
    for (int i = 0; i < 8; i++)
        #pragma unroll
        for (int j = 0; j < 4; j++)
            *(float2*)&g_scores[((size_t)b * HH + hg * 8 + i) * TOTALN + s0 + sg * 2 + j * 64]
                = acc[i][j];
}

// ---------------- K4: softmax over 8192 per (b,h) ----------------
__global__ __launch_bounds__(256) void k_softmax() {
    int bh = blockIdx.x;
    int tid = threadIdx.x;
    int w = tid >> 5, lane = tid & 31;
    float* row = g_scores + (size_t)bh * TOTALN;
    float4 v[8];
    #pragma unroll
    for (int i = 0; i < 8; i++) v[i] = ((float4*)row)[tid * 8 + i];
    float m = -1e30f;
    #pragma unroll
    for (int i = 0; i < 8; i++)
        m = fmaxf(m, fmaxf(fmaxf(v[i].x, v[i].y), fmaxf(v[i].z, v[i].w)));
    #pragma unroll
    for (int o = 16; o; o >>= 1) m = fmaxf(m, __shfl_xor_sync(0xffffffffu, m, o));
    __shared__ float redm[8], reds[8];
    if (lane == 0) redm[w] = m;
    __syncthreads();
    m = redm[0];
    #pragma unroll
    for (int i = 1; i < 8; i++) m = fmaxf(m, redm[i]);
    float s = 0.f;
    #pragma unroll
    for (int i = 0; i < 8; i++) {
        v[i].x = __expf(v[i].x - m); v[i].y = __expf(v[i].y - m);
        v[i].z = __expf(v[i].z - m); v[i].w = __expf(v[i].w - m);
        s += v[i].x + v[i].y + v[i].z + v[i].w;
    }
    #pragma unroll
    for (int o = 16; o; o >>= 1) s += __shfl_xor_sync(0xffffffffu, s, o);
    if (lane == 0) reds[w] = s;
    __syncthreads();
    s = reds[0] + reds[1] + reds[2] + reds[3] + reds[4] + reds[5] + reds[6] + reds[7];
    float inv = 1.f / s;
    #pragma unroll
    for (int i = 0; i < 8; i++) {
        v[i].x *= inv; v[i].y *= inv; v[i].z *= inv; v[i].w *= inv;
        ((float4*)row)[tid * 8 + i] = v[i];
    }
}

// ---------------- K5: o_c partials = attn @ c_full  (s-split over 16) ----------------
// grid (sc=16, b=8); 256 threads; per-thread 8h x 4 n-pairs
__global__ __launch_bounds__(256) void k_ov(const float* __restrict__ past_c) {
    extern __shared__ float sm[];
    float* c_s = sm;                                   // [64 s][512 n]
    float2* ad = (float2*)(sm + 64 * 512);             // [32 h][64 s] duplicated
    int sc = blockIdx.x, b = blockIdx.y;
    int tid = threadIdx.x;
    int hg = tid >> 6;     // 4 groups x 8h (uniform per warp -> broadcast)
    int ng = tid & 63;
    float2 acc[8][4];
    #pragma unroll
    for (int i = 0; i < 8; i++)
        #pragma unroll
        for (int j = 0; j < 4; j++) acc[i][j] = make_float2(0.f, 0.f);

    for (int ch = 0; ch < 8; ch++) {
        int s0 = sc * 512 + ch * 64;
        if (ch) __syncthreads();
        for (int i = tid; i < 64 * 128; i += 256) {    // 8192 float4
            int s = i >> 7, nq = i & 127;
            const float* row = (s0 + s < PASTN) ? past_c + ((size_t)b * PASTN + s0 + s) * KVV
                                                : g_cnew + b * KVV;
            ((float4*)c_s)[s * 128 + nq] = *(const float4*)(row + nq * 4);
        }
        for (int i = tid; i < 32 * 64; i += 256) {
            int hh = i >> 6, s2 = i & 63;
            float a = g_scores[((size_t)b * HH + hh) * TOTALN + s0 + s2];
            ad[hh * 64 + s2] = make_float2(a, a);
        }
        __syncthreads();
        #pragma unroll 2
        for (int s = 0; s < 64; s++) {
            float2 a[8];
            #pragma unroll
            for (int i = 0; i < 8; i++) a[i] = ad[(hg * 8 + i) * 64 + s];
            #pragma unroll
            for (int j = 0; j < 4; j++) {
                float2 c2 = *(const float2*)&c_s[s * 512 + ng * 2 + j * 128];
                #pragma unroll
                for (int i = 0; i < 8; i++)
                    acc[i][j] = ffma2(a[i], c2, acc[i][j]);
            }
        }
    }
    #pragma unroll
    for (int i = 0; i < 8; i++)
        #pragma unroll
        for (int j = 0; j < 4; j++)
            *(float2*)&g_opart[(((size_t)sc * BB + b) * HH + hg * 8 + i) * KVV
                               + ng * 2 + j * 128] = acc[i][j];
}

// reduce 16 s-partials -> g_oc
__global__ void k_redo() {
    int i = blockIdx.x * 256 + threadIdx.x;
    const float4* p = (const float4*)g_opart;
    float4 s = make_float4(0.f, 0.f, 0.f, 0.f);
    #pragma unroll
    for (int c = 0; c < 16; c++) {
        float4 t = p[c * 32768 + i];
        s.x += t.x; s.y += t.y; s.z += t.z; s.w += t.w;
    }
    ((float4*)g_oc)[i] = s;
}

// ---------------- K6: per-head v-up: out_head = o_c @ w_v[:,h,:] ----------------
__global__ __launch_bounds__(64) void k_vup(const float* __restrict__ wv) {
    __shared__ float2 ocd[BB * KVV];   // duplicated
    int h = blockIdx.x;
    int tid = threadIdx.x;             // 64; owns j-pair tid*2
    for (int i = tid; i < BB * KVV; i += 64) {
        float v = g_oc[((size_t)(i >> 9) * HH + h) * KVV + (i & 511)];
        ocd[i] = make_float2(v, v);
    }
    __syncthreads();
    float2 acc[BB];
    #pragma unroll
    for (int b = 0; b < BB; b++) acc[b] = make_float2(0.f, 0.f);
    const float* wp = wv + h * HDD + tid * 2;
    #pragma unroll 4
    for (int n = 0; n < KVV; n++) {
        float2 w2 = *(const float2*)(wp + (size_t)n * (HH * HDD));
        #pragma unroll
        for (int b = 0; b < BB; b++)
            acc[b] = ffma2(ocd[b * KVV + n], w2, acc[b]);
    }
    #pragma unroll
    for (int b = 0; b < BB; b++)
        *(float2*)&g_ohead[b * DD + h * HDD + tid * 2] = acc[b];
}

// ---------------- K7: out = out_head @ w_o  (m-split, atomic) ----------------
// grid (dt=16 d-tiles of 256, mc=8 m-chunks of 512); 128 threads
__global__ __launch_bounds__(128) void k_oproj(const float* __restrict__ wo,
                                               float* __restrict__ out) {
    __shared__ float2 ohd[BB * 512];
    int dt = blockIdx.x, mc = blockIdx.y;
    int tid = threadIdx.x;
    for (int i = tid; i < BB * 512; i += 128) {
        float v = g_ohead[(i >> 9) * DD + mc * 512 + (i & 511)];
        ohd[i] = make_float2(v, v);
    }
    __syncthreads();
    float2 acc[BB];
    #pragma unroll
    for (int b = 0; b < BB; b++) acc[b] = make_float2(0.f, 0.f);
    const float* wp = wo + (size_t)mc * 512 * DD + dt * 256 + tid * 2;
    #pragma unroll 4
    for (int m = 0; m < 512; m++) {
        float2 w2 = *(const float2*)(wp + (size_t)m * DD);
        #pragma unroll
        for (int b = 0; b < BB; b++)
            acc[b] = ffma2(ohd[b * 512 + m], w2, acc[b]);
    }
    #pragma unroll
    for (int b = 0; b < BB; b++) {
        atomicAdd(&out[b * DD + dt * 256 + tid * 2 + 0], acc[b].x);
        atomicAdd(&out[b * DD + dt * 256 + tid * 2 + 1], acc[b].y);
    }
}

// ---------------- launch ----------------
extern "C" void kernel_launch(void* const* d_in, const int* in_sizes, int n_in,
                              void* d_out, int out_size) {
    const float* x      = (const float*)d_in[0];
    const float* past_c = (const float*)d_in[1];
    const float* aqk    = (const float*)d_in[2];
    const float* wc     = (const float*)d_in[3];
    const float* wv     = (const float*)d_in[4];
    const float* wo     = (const float*)d_in[5];
    float* out = (float*)d_out;

    const int SMEM_K3 = 64 * 258 * 4 + 32 * 64 * 8;   // 82432
    const int SMEM_K5 = 64 * 512 * 4 + 32 * 64 * 8;   // 147456
    cudaFuncSetAttribute(k_scores, cudaFuncAttributeMaxDynamicSharedMemorySize, SMEM_K3);
    cudaFuncSetAttribute(k_ov,     cudaFuncAttributeMaxDynamicSharedMemorySize, SMEM_K5);

    k_init<<<128, 256>>>(out);
    k_compress<<<32, 256>>>(x, wc);
    k_qabs<<<dim3(8, 32), 256>>>(x, aqk);
    k_redq<<<128, 256>>>();
    k_scores<<<dim3(32, 8), 128, SMEM_K3>>>(past_c);
    k_softmax<<<256, 256>>>();
    k_ov<<<dim3(16, 8), 256, SMEM_K5>>>(past_c);
    k_redo<<<128, 256>>>();
    k_vup<<<32, 64>>>(wv);
    k_oproj<<<dim3(16, 8), 128>>>(wo, out);
}

// round 3
// speedup vs baseline: 1.2408x; 1.2408x over previous
#include <cuda_runtime.h>

#define BB 8
#define DD 4096
#define HH 32
#define HDD 128
#define KVV 512
#define PASTN 8191
#define TOTALN 8192
#define SCALEF 0.08838834764831845f  // 128^-0.5

// ---------------- scratch (static device globals; no allocation) ----------------
__device__ float g_cnew[BB * KVV];
__device__ float g_qpart[8 * BB * HH * KVV];
__device__ float g_qabs[BB * HH * KVV];
__device__ float g_scores[BB * HH * TOTALN];
__device__ float g_opart[16 * BB * HH * KVV];
__device__ float g_oc[BB * HH * KVV];
__device__ float g_ohead[BB * HH * HDD];

// packed dual-fp32 FMA (sm_100+)
__device__ __forceinline__ float2 ffma2(const float2 a, const float2 b, const float2 c) {
    float2 d;
    asm("fma.rn.f32x2 %0, %1, %2, %3;"
        : "=l"(*(unsigned long long*)&d)
        : "l"(*(const unsigned long long*)&a),
          "l"(*(const unsigned long long*)&b),
          "l"(*(const unsigned long long*)&c));
    return d;
}

// ---------------- K0: zero d_out, g_cnew, g_ohead ----------------
__global__ void k_init(float* __restrict__ out) {
    int i = blockIdx.x * 256 + threadIdx.x;       // 32768 threads
    out[i] = 0.f;
    g_ohead[i] = 0.f;
    if (i < BB * KVV) g_cnew[i] = 0.f;
}

// ---------------- K1: c_new[b] = x[b] @ w_compress  (k-split, atomic) ----------------
__global__ __launch_bounds__(256) void k_compress(const float* __restrict__ x,
                                                  const float* __restrict__ wc) {
    __shared__ float xs[128][8];   // [k][b]
    int kc = blockIdx.x;           // 32 chunks of 128 k
    int tid = threadIdx.x;
    for (int i = tid; i < BB * 128; i += 256) {
        int b = i >> 7, k = i & 127;
        xs[k][b] = x[b * DD + kc * 128 + k];
    }
    __syncthreads();
    float2 acc[BB];
    #pragma unroll
    for (int b = 0; b < BB; b++) acc[b] = make_float2(0.f, 0.f);
    const float* wp = wc + (size_t)kc * 128 * KVV + tid * 2;
    #pragma unroll 8
    for (int k = 0; k < 128; k++) {
        float2 w2 = *(const float2*)(wp + (size_t)k * KVV);
        float4 x0 = *(const float4*)&xs[k][0];
        float4 x1 = *(const float4*)&xs[k][4];
        acc[0] = ffma2(make_float2(x0.x, x0.x), w2, acc[0]);
        acc[1] = ffma2(make_float2(x0.y, x0.y), w2, acc[1]);
        acc[2] = ffma2(make_float2(x0.z, x0.z), w2, acc[2]);
        acc[3] = ffma2(make_float2(x0.w, x0.w), w2, acc[3]);
        acc[4] = ffma2(make_float2(x1.x, x1.x), w2, acc[4]);
        acc[5] = ffma2(make_float2(x1.y, x1.y), w2, acc[5]);
        acc[6] = ffma2(make_float2(x1.z, x1.z), w2, acc[6]);
        acc[7] = ffma2(make_float2(x1.w, x1.w), w2, acc[7]);
    }
    #pragma unroll
    for (int b = 0; b < BB; b++) {
        atomicAdd(&g_cnew[b * KVV + tid * 2 + 0], acc[b].x);
        atomicAdd(&g_cnew[b * KVV + tid * 2 + 1], acc[b].y);
    }
}

// ---------------- K2: q_abs partials (scale folded into x) ----------------
// grid (kc=8, h=32); 256 threads; thread owns n-pair tid*2, all 8 batches
__global__ __launch_bounds__(256) void k_qabs(const float* __restrict__ x,
                                              const float* __restrict__ aqk) {
    __shared__ float xs[512][8];   // [k][b], pre-scaled
    int kc = blockIdx.x;
    int h  = blockIdx.y;
    int tid = threadIdx.x;
    for (int i = tid; i < BB * 512; i += 256) {
        int b = i >> 9, k = i & 511;
        xs[k][b] = x[b * DD + kc * 512 + k] * SCALEF;
    }
    __syncthreads();
    float2 acc[BB];
    #pragma unroll
    for (int b = 0; b < BB; b++) acc[b] = make_float2(0.f, 0.f);
    const float* ap = aqk + ((size_t)h * DD + (size_t)kc * 512) * KVV + tid * 2;
    #pragma unroll 8
    for (int k = 0; k < 512; k++) {
        float2 a2 = *(const float2*)(ap + (size_t)k * KVV);
        float4 x0 = *(const float4*)&xs[k][0];
        float4 x1 = *(const float4*)&xs[k][4];
        acc[0] = ffma2(a2, make_float2(x0.x, x0.x), acc[0]);
        acc[1] = ffma2(a2, make_float2(x0.y, x0.y), acc[1]);
        acc[2] = ffma2(a2, make_float2(x0.z, x0.z), acc[2]);
        acc[3] = ffma2(a2, make_float2(x0.w, x0.w), acc[3]);
        acc[4] = ffma2(a2, make_float2(x1.x, x1.x), acc[4]);
        acc[5] = ffma2(a2, make_float2(x1.y, x1.y), acc[5]);
        acc[6] = ffma2(a2, make_float2(x1.z, x1.z), acc[6]);
        acc[7] = ffma2(a2, make_float2(x1.w, x1.w), acc[7]);
    }
    #pragma unroll
    for (int b = 0; b < BB; b++)
        *(float2*)&g_qpart[((size_t)(kc * BB + b) * HH + h) * KVV + tid * 2] = acc[b];
}

// reduce 8 k-partials -> g_qabs
__global__ void k_redq() {
    int i = blockIdx.x * 256 + threadIdx.x;   // 32768 float4 columns
    const float4* p = (const float4*)g_qpart;
    float4 s = make_float4(0.f, 0.f, 0.f, 0.f);
    #pragma unroll
    for (int c = 0; c < 8; c++) {
        float4 t = p[c * 32768 + i];
        s.x += t.x; s.y += t.y; s.z += t.z; s.w += t.w;
    }
    ((float4*)g_qabs)[i] = s;
}

// ---------------- K3: scores[b,h,s] = q_abs[b,h,:] . c_full[b,s,:] ----------------
// grid (st=32 s-tiles of 256, b=8); 128 threads; per-thread 8h x 8s (4 float2)
__global__ __launch_bounds__(128) void k_scores(const float* __restrict__ past_c) {
    extern __shared__ float sm[];
    float*  c_s = sm;                                   // [64 k][258 s] transposed
    float2* qd  = (float2*)(sm + 64 * 258);             // [64 k][32 h] dup pairs
    int st = blockIdx.x, b = blockIdx.y;
    int tid = threadIdx.x;
    int w = tid >> 5, lane = tid & 31;
    int hg = w;          // h-octet per warp -> broadcast q loads
    int sg = lane;
    int s0 = st * 256;
    float2 acc[8][4];
    #pragma unroll
    for (int i = 0; i < 8; i++)
        #pragma unroll
        for (int j = 0; j < 4; j++) acc[i][j] = make_float2(0.f, 0.f);

    for (int kc = 0; kc < 8; kc++) {
        // c chunk transposed: c_s[k][s]
        #pragma unroll
        for (int ss = 0; ss < 2; ss++) {
            int s = ss * 128 + w * 32 + lane;
            int sa = s0 + s;
            const float* row = (sa < PASTN) ? past_c + ((size_t)b * PASTN + sa) * KVV
                                            : g_cnew + b * KVV;
            #pragma unroll
            for (int kq = 0; kq < 16; kq++) {
                float4 v = *(const float4*)(row + kc * 64 + kq * 4);
                c_s[(kq * 4 + 0) * 258 + s] = v.x;
                c_s[(kq * 4 + 1) * 258 + s] = v.y;
                c_s[(kq * 4 + 2) * 258 + s] = v.z;
                c_s[(kq * 4 + 3) * 258 + s] = v.w;
            }
        }
        // q chunk, duplicated, packed [k][h]
        for (int i = tid; i < 64 * 32; i += 128) {
            int k = i >> 5, hh = i & 31;
            float q = g_qabs[((size_t)b * HH + hh) * KVV + kc * 64 + k];
            qd[k * 32 + hh] = make_float2(q, q);
        }
        __syncthreads();
        #pragma unroll 2
        for (int k = 0; k < 64; k++) {
            const float4* qp = (const float4*)(qd + k * 32 + hg * 8);
            float4 q0 = qp[0], q1 = qp[1], q2 = qp[2], q3 = qp[3];
            float2 c2[4];
            #pragma unroll
            for (int j = 0; j < 4; j++)
                c2[j] = *(const float2*)&c_s[k * 258 + sg * 2 + j * 64];
            #pragma unroll
            for (int j = 0; j < 4; j++) {
                acc[0][j] = ffma2(make_float2(q0.x, q0.y), c2[j], acc[0][j]);
                acc[1][j] = ffma2(make_float2(q0.z, q0.w), c2[j], acc[1][j]);
                acc[2][j] = ffma2(make_float2(q1.x, q1.y), c2[j], acc[2][j]);
                acc[3][j] = ffma2(make_float2(q1.z, q1.w), c2[j], acc[3][j]);
                acc[4][j] = ffma2(make_float2(q2.x, q2.y), c2[j], acc[4][j]);
                acc[5][j] = ffma2(make_float2(q2.z, q2.w), c2[j], acc[5][j]);
                acc[6][j] = ffma2(make_float2(q3.x, q3.y), c2[j], acc[6][j]);
                acc[7][j] = ffma2(make_float2(q3.z, q3.w), c2[j], acc[7][j]);
            }
        }
        __syncthreads();
    }
    #pragma unroll
    for (int i = 0; i < 8; i++)
        #pragma unroll
        for (int j = 0; j < 4; j++)
            *(float2*)&g_scores[((size_t)b * HH + hg * 8 + i) * TOTALN + s0 + sg * 2 + j * 64]
                = acc[i][j];
}

// ---------------- K4: softmax over 8192 per (b,h) ----------------
__global__ __launch_bounds__(256) void k_softmax() {
    int bh = blockIdx.x;
    int tid = threadIdx.x;
    int w = tid >> 5, lane = tid & 31;
    float* row = g_scores + (size_t)bh * TOTALN;
    float4 v[8];
    #pragma unroll
    for (int i = 0; i < 8; i++) v[i] = ((float4*)row)[tid * 8 + i];
    float m = -1e30f;
    #pragma unroll
    for (int i = 0; i < 8; i++)
        m = fmaxf(m, fmaxf(fmaxf(v[i].x, v[i].y), fmaxf(v[i].z, v[i].w)));
    #pragma unroll
    for (int o = 16; o; o >>= 1) m = fmaxf(m, __shfl_xor_sync(0xffffffffu, m, o));
    __shared__ float redm[8], reds[8];
    if (lane == 0) redm[w] = m;
    __syncthreads();
    m = redm[0];
    #pragma unroll
    for (int i = 1; i < 8; i++) m = fmaxf(m, redm[i]);
    float s = 0.f;
    #pragma unroll
    for (int i = 0; i < 8; i++) {
        v[i].x = __expf(v[i].x - m); v[i].y = __expf(v[i].y - m);
        v[i].z = __expf(v[i].z - m); v[i].w = __expf(v[i].w - m);
        s += v[i].x + v[i].y + v[i].z + v[i].w;
    }
    #pragma unroll
    for (int o = 16; o; o >>= 1) s += __shfl_xor_sync(0xffffffffu, s, o);
    if (lane == 0) reds[w] = s;
    __syncthreads();
    s = reds[0] + reds[1] + reds[2] + reds[3] + reds[4] + reds[5] + reds[6] + reds[7];
    float inv = 1.f / s;
    #pragma unroll
    for (int i = 0; i < 8; i++) {
        v[i].x *= inv; v[i].y *= inv; v[i].z *= inv; v[i].w *= inv;
        ((float4*)row)[tid * 8 + i] = v[i];
    }
}

// ---------------- K5: o_c partials = attn @ c_full  (s-split over 16) ----------------
// grid (sc=16, b=8); 256 threads; per-thread 8h x 8n (4 float2)
__global__ __launch_bounds__(256) void k_ov(const float* __restrict__ past_c) {
    extern __shared__ float sm[];
    float*  c_s = sm;                                   // [64 s][512 n]
    float2* ad  = (float2*)(sm + 64 * 512);             // [64 s][32 h] dup pairs
    int sc = blockIdx.x, b = blockIdx.y;
    int tid = threadIdx.x;
    int hg = tid >> 6;     // 4 groups x 8h (warp-uniform -> broadcast)
    int ng = tid & 63;
    float2 acc[8][4];
    #pragma unroll
    for (int i = 0; i < 8; i++)
        #pragma unroll
        for (int j = 0; j < 4; j++) acc[i][j] = make_float2(0.f, 0.f);

    for (int ch = 0; ch < 8; ch++) {
        int s0 = sc * 512 + ch * 64;
        if (ch) __syncthreads();
        for (int i = tid; i < 64 * 128; i += 256) {    // 8192 float4
            int s = i >> 7, nq = i & 127;
            const float* row = (s0 + s < PASTN) ? past_c + ((size_t)b * PASTN + s0 + s) * KVV
                                                : g_cnew + b * KVV;
            ((float4*)c_s)[s * 128 + nq] = *(const float4*)(row + nq * 4);
        }
        for (int i = tid; i < 64 * 32; i += 256) {
            int s2 = i >> 5, hh = i & 31;
            float a = g_scores[((size_t)b * HH + hh) * TOTALN + s0 + s2];
            ad[s2 * 32 + hh] = make_float2(a, a);
        }
        __syncthreads();
        #pragma unroll 2
        for (int s = 0; s < 64; s++) {
            const float4* ap4 = (const float4*)(ad + s * 32 + hg * 8);
            float4 a0 = ap4[0], a1 = ap4[1], a2 = ap4[2], a3 = ap4[3];
            float2 c2[4];
            #pragma unroll
            for (int j = 0; j < 4; j++)
                c2[j] = *(const float2*)&c_s[s * 512 + ng * 2 + j * 128];
            #pragma unroll
            for (int j = 0; j < 4; j++) {
                acc[0][j] = ffma2(make_float2(a0.x, a0.y), c2[j], acc[0][j]);
                acc[1][j] = ffma2(make_float2(a0.z, a0.w), c2[j], acc[1][j]);
                acc[2][j] = ffma2(make_float2(a1.x, a1.y), c2[j], acc[2][j]);
                acc[3][j] = ffma2(make_float2(a1.z, a1.w), c2[j], acc[3][j]);
                acc[4][j] = ffma2(make_float2(a2.x, a2.y), c2[j], acc[4][j]);
                acc[5][j] = ffma2(make_float2(a2.z, a2.w), c2[j], acc[5][j]);
                acc[6][j] = ffma2(make_float2(a3.x, a3.y), c2[j], acc[6][j]);
                acc[7][j] = ffma2(make_float2(a3.z, a3.w), c2[j], acc[7][j]);
            }
        }
    }
    #pragma unroll
    for (int i = 0; i < 8; i++)
        #pragma unroll
        for (int j = 0; j < 4; j++)
            *(float2*)&g_opart[(((size_t)sc * BB + b) * HH + hg * 8 + i) * KVV
                               + ng * 2 + j * 128] = acc[i][j];
}

// reduce 16 s-partials -> g_oc
__global__ void k_redo() {
    int i = blockIdx.x * 256 + threadIdx.x;
    const float4* p = (const float4*)g_opart;
    float4 s = make_float4(0.f, 0.f, 0.f, 0.f);
    #pragma unroll
    for (int c = 0; c < 16; c++) {
        float4 t = p[c * 32768 + i];
        s.x += t.x; s.y += t.y; s.z += t.z; s.w += t.w;
    }
    ((float4*)g_oc)[i] = s;
}

// ---------------- K6: per-head v-up (n-split, atomic) ----------------
// grid (h=32, nc=4); 128 threads: jp = tid&63 (j-pair), g = tid>>6 (n-half)
__global__ __launch_bounds__(128) void k_vup(const float* __restrict__ wv) {
    __shared__ float od[128][8];   // [n_local][b]
    int h = blockIdx.x, nc = blockIdx.y;
    int tid = threadIdx.x;
    int jp = tid & 63, g = tid >> 6;
    for (int i = tid; i < 128 * 8; i += 128) {
        int b = i >> 7, n = i & 127;
        od[n][b] = g_oc[((size_t)b * HH + h) * KVV + nc * 128 + n];
    }
    __syncthreads();
    float2 acc[BB];
    #pragma unroll
    for (int b = 0; b < BB; b++) acc[b] = make_float2(0.f, 0.f);
    const float* wp = wv + (size_t)(nc * 128 + g * 64) * (HH * HDD) + h * HDD + jp * 2;
    #pragma unroll 8
    for (int n = 0; n < 64; n++) {
        float2 w2 = *(const float2*)(wp + (size_t)n * (HH * HDD));
        float4 o0 = *(const float4*)&od[g * 64 + n][0];
        float4 o1 = *(const float4*)&od[g * 64 + n][4];
        acc[0] = ffma2(make_float2(o0.x, o0.x), w2, acc[0]);
        acc[1] = ffma2(make_float2(o0.y, o0.y), w2, acc[1]);
        acc[2] = ffma2(make_float2(o0.z, o0.z), w2, acc[2]);
        acc[3] = ffma2(make_float2(o0.w, o0.w), w2, acc[3]);
        acc[4] = ffma2(make_float2(o1.x, o1.x), w2, acc[4]);
        acc[5] = ffma2(make_float2(o1.y, o1.y), w2, acc[5]);
        acc[6] = ffma2(make_float2(o1.z, o1.z), w2, acc[6]);
        acc[7] = ffma2(make_float2(o1.w, o1.w), w2, acc[7]);
    }
    #pragma unroll
    for (int b = 0; b < BB; b++) {
        atomicAdd(&g_ohead[b * DD + h * HDD + jp * 2 + 0], acc[b].x);
        atomicAdd(&g_ohead[b * DD + h * HDD + jp * 2 + 1], acc[b].y);
    }
}

// ---------------- K7: out = out_head @ w_o  (m-split over 16, atomic) ----------------
// grid (dt=16 d-tiles of 256, mc=16 m-chunks of 256); 128 threads
__global__ __launch_bounds__(128) void k_oproj(const float* __restrict__ wo,
                                               float* __restrict__ out) {
    __shared__ float ohd[256][8];   // [m_local][b]
    int dt = blockIdx.x, mc = blockIdx.y;
    int tid = threadIdx.x;
    for (int i = tid; i < 256 * 8; i += 128) {
        int b = i >> 8, m = i & 255;
        ohd[m][b] = g_ohead[b * DD + mc * 256 + m];
    }
    __syncthreads();
    float2 acc[BB];
    #pragma unroll
    for (int b = 0; b < BB; b++) acc[b] = make_float2(0.f, 0.f);
    const float* wp = wo + (size_t)mc * 256 * DD + dt * 256 + tid * 2;
    #pragma unroll 8
    for (int m = 0; m < 256; m++) {
        float2 w2 = *(const float2*)(wp + (size_t)m * DD);
        float4 o0 = *(const float4*)&ohd[m][0];
        float4 o1 = *(const float4*)&ohd[m][4];
        acc[0] = ffma2(make_float2(o0.x, o0.x), w2, acc[0]);
        acc[1] = ffma2(make_float2(o0.y, o0.y), w2, acc[1]);
        acc[2] = ffma2(make_float2(o0.z, o0.z), w2, acc[2]);
        acc[3] = ffma2(make_float2(o0.w, o0.w), w2, acc[3]);
        acc[4] = ffma2(make_float2(o1.x, o1.x), w2, acc[4]);
        acc[5] = ffma2(make_float2(o1.y, o1.y), w2, acc[5]);
        acc[6] = ffma2(make_float2(o1.z, o1.z), w2, acc[6]);
        acc[7] = ffma2(make_float2(o1.w, o1.w), w2, acc[7]);
    }
    #pragma unroll
    for (int b = 0; b < BB; b++) {
        atomicAdd(&out[b * DD + dt * 256 + tid * 2 + 0], acc[b].x);
        atomicAdd(&out[b * DD + dt * 256 + tid * 2 + 1], acc[b].y);
    }
}

// ---------------- launch ----------------
extern "C" void kernel_launch(void* const* d_in, const int* in_sizes, int n_in,
                              void* d_out, int out_size) {
    const float* x      = (const float*)d_in[0];
    const float* past_c = (const float*)d_in[1];
    const float* aqk    = (const float*)d_in[2];
    const float* wc     = (const float*)d_in[3];
    const float* wv     = (const float*)d_in[4];
    const float* wo     = (const float*)d_in[5];
    float* out = (float*)d_out;

    const int SMEM_K3 = 64 * 258 * 4 + 64 * 32 * 8;   // 82432
    const int SMEM_K5 = 64 * 512 * 4 + 64 * 32 * 8;   // 147456
    cudaFuncSetAttribute(k_scores, cudaFuncAttributeMaxDynamicSharedMemorySize, SMEM_K3);
    cudaFuncSetAttribute(k_ov,     cudaFuncAttributeMaxDynamicSharedMemorySize, SMEM_K5);

    k_init<<<128, 256>>>(out);
    k_compress<<<32, 256>>>(x, wc);
    k_qabs<<<dim3(8, 32), 256>>>(x, aqk);
    k_redq<<<128, 256>>>();
    k_scores<<<dim3(32, 8), 128, SMEM_K3>>>(past_c);
    k_softmax<<<256, 256>>>();
    k_ov<<<dim3(16, 8), 256, SMEM_K5>>>(past_c);
    k_redo<<<128, 256>>>();
    k_vup<<<dim3(32, 4), 128>>>(wv);
    k_oproj<<<dim3(16, 16), 128>>>(wo, out);
}

// round 4
// speedup vs baseline: 1.3350x; 1.0759x over previous
#include <cuda_runtime.h>

#define BB 8
#define DD 4096
#define HH 32
#define HDD 128
#define KVV 512
#define PASTN 8191
#define TOTALN 8192
#define SCALEF 0.08838834764831845f  // 128^-0.5

// ---------------- scratch ----------------
__device__ float g_cnew[BB * KVV];
__device__ float g_qpart[8 * BB * HH * KVV];
__device__ float g_qabs[BB * HH * KVV];
__device__ float g_scores[BB * HH * TOTALN];
__device__ float g_opart[16 * BB * HH * KVV];
__device__ float g_oc[BB * HH * KVV];
__device__ float g_ohead[BB * HH * HDD];

// packed dual-fp32 FMA (sm_100+)
__device__ __forceinline__ float2 ffma2(const float2 a, const float2 b, const float2 c) {
    float2 d;
    asm("fma.rn.f32x2 %0, %1, %2, %3;"
        : "=l"(*(unsigned long long*)&d)
        : "l"(*(const unsigned long long*)&a),
          "l"(*(const unsigned long long*)&b),
          "l"(*(const unsigned long long*)&c));
    return d;
}

__device__ __forceinline__ void cp_async16(unsigned s, const void* g) {
    asm volatile("cp.async.cg.shared.global [%0], [%1], 16;" :: "r"(s), "l"(g));
}
__device__ __forceinline__ void cp_commit() {
    asm volatile("cp.async.commit_group;");
}

// ---------------- K0: zero d_out, g_cnew, g_ohead ----------------
__global__ void k_init(float* __restrict__ out) {
    int i = blockIdx.x * 256 + threadIdx.x;       // 32768
    out[i] = 0.f;
    g_ohead[i] = 0.f;
    if (i < BB * KVV) g_cnew[i] = 0.f;
}

// ---------------- K1: c_new = x @ w_compress (k-split, atomic) ----------------
__global__ __launch_bounds__(256) void k_compress(const float* __restrict__ x,
                                                  const float* __restrict__ wc) {
    __shared__ float2 xd[128][8];   // [k][b] dup pairs
    int kc = blockIdx.x;            // 32 chunks of 128 k
    int tid = threadIdx.x;
    for (int i = tid; i < 1024; i += 256) {
        int k = i >> 3, b = i & 7;
        float v = x[b * DD + kc * 128 + k];
        xd[k][b] = make_float2(v, v);
    }
    __syncthreads();
    float2 acc[BB];
    #pragma unroll
    for (int b = 0; b < BB; b++) acc[b] = make_float2(0.f, 0.f);
    const float* wp = wc + (size_t)kc * 128 * KVV + tid * 2;
    #pragma unroll 8
    for (int k = 0; k < 128; k++) {
        float2 w2 = *(const float2*)(wp + (size_t)k * KVV);
        #pragma unroll
        for (int b = 0; b < BB; b++)
            acc[b] = ffma2(xd[k][b], w2, acc[b]);
    }
    #pragma unroll
    for (int b = 0; b < BB; b++) {
        atomicAdd(&g_cnew[b * KVV + tid * 2 + 0], acc[b].x);
        atomicAdd(&g_cnew[b * KVV + tid * 2 + 1], acc[b].y);
    }
}

// ---------------- K2: q_abs partials (scale folded into x) ----------------
// grid (kc=8, h=32); 128 threads; thread owns n-quad tid*4
__global__ __launch_bounds__(128) void k_qabs(const float* __restrict__ x,
                                              const float* __restrict__ aqk) {
    __shared__ float2 xd[512][8];   // [k][b] dup pairs, pre-scaled (32KB)
    int kc = blockIdx.x;
    int h  = blockIdx.y;
    int tid = threadIdx.x;
    for (int i = tid; i < 4096; i += 128) {
        int k = i >> 3, b = i & 7;
        float v = x[b * DD + kc * 512 + k] * SCALEF;
        xd[k][b] = make_float2(v, v);
    }
    __syncthreads();
    float2 acc[BB][2];
    #pragma unroll
    for (int b = 0; b < BB; b++) {
        acc[b][0] = make_float2(0.f, 0.f);
        acc[b][1] = make_float2(0.f, 0.f);
    }
    const float* ap = aqk + ((size_t)h * DD + (size_t)kc * 512) * KVV + tid * 4;
    #pragma unroll 8
    for (int k = 0; k < 512; k++) {
        float4 a4 = *(const float4*)(ap + (size_t)k * KVV);
        float2 alo = make_float2(a4.x, a4.y);
        float2 ahi = make_float2(a4.z, a4.w);
        #pragma unroll
        for (int b = 0; b < BB; b++) {
            float2 xb = xd[k][b];
            acc[b][0] = ffma2(alo, xb, acc[b][0]);
            acc[b][1] = ffma2(ahi, xb, acc[b][1]);
        }
    }
    #pragma unroll
    for (int b = 0; b < BB; b++) {
        float4 r = make_float4(acc[b][0].x, acc[b][0].y, acc[b][1].x, acc[b][1].y);
        *(float4*)&g_qpart[((size_t)(kc * BB + b) * HH + h) * KVV + tid * 4] = r;
    }
}

// reduce 8 k-partials -> g_qabs
__global__ void k_redq() {
    int i = blockIdx.x * 256 + threadIdx.x;   // 32768 float4 columns
    const float4* p = (const float4*)g_qpart;
    float4 s = make_float4(0.f, 0.f, 0.f, 0.f);
    #pragma unroll
    for (int c = 0; c < 8; c++) {
        float4 t = p[c * 32768 + i];
        s.x += t.x; s.y += t.y; s.z += t.z; s.w += t.w;
    }
    ((float4*)g_qabs)[i] = s;
}

// ---------------- K3: scores — warp-specialized producer/consumer ----------------
// grid (st=32, b=8); 256 threads: warps 0-3 produce tiles, warps 4-7 compute.
__device__ __forceinline__ void fill_tile(float* __restrict__ c_s, float2* __restrict__ qd,
                                          const float* __restrict__ past_c,
                                          int b, int s0, int kc, int ptid) {
    #pragma unroll
    for (int ss = 0; ss < 2; ss++) {
        int s = ss * 128 + ptid;
        int sa = s0 + s;
        const float* row = (sa < PASTN) ? past_c + ((size_t)b * PASTN + sa) * KVV
                                        : g_cnew + b * KVV;
        #pragma unroll
        for (int kq = 0; kq < 16; kq++) {
            float4 v = *(const float4*)(row + kc * 64 + kq * 4);
            c_s[(kq * 4 + 0) * 258 + s] = v.x;
            c_s[(kq * 4 + 1) * 258 + s] = v.y;
            c_s[(kq * 4 + 2) * 258 + s] = v.z;
            c_s[(kq * 4 + 3) * 258 + s] = v.w;
        }
    }
    #pragma unroll
    for (int t = 0; t < 16; t++) {
        int i = ptid + t * 128;
        int k = i >> 5, hh = i & 31;
        float q = g_qabs[((size_t)b * HH + hh) * KVV + kc * 64 + k];
        qd[k * 32 + hh] = make_float2(q, q);
    }
}

__global__ __launch_bounds__(256) void k_scores(const float* __restrict__ past_c) {
    extern __shared__ float sm[];
    float*  cb0 = sm;                         // 16512 floats
    float*  cb1 = sm + 16512;
    float2* qb0 = (float2*)(sm + 2 * 16512);  // 2048 float2
    float2* qb1 = qb0 + 2048;
    int st = blockIdx.x, b = blockIdx.y;
    int tid = threadIdx.x;
    int w = tid >> 5, lane = tid & 31;
    int s0 = st * 256;
    bool prod = (w < 4);

    if (prod) fill_tile(cb0, qb0, past_c, b, s0, 0, tid);

    float2 acc[8][4];
    #pragma unroll
    for (int i = 0; i < 8; i++)
        #pragma unroll
        for (int j = 0; j < 4; j++) acc[i][j] = make_float2(0.f, 0.f);
    __syncthreads();

    int hg = w - 4, sg = lane;
    for (int kc = 0; kc < 8; kc++) {
        if (prod) {
            if (kc < 7)
                fill_tile((kc & 1) ? cb0 : cb1, (kc & 1) ? qb0 : qb1,
                          past_c, b, s0, kc + 1, tid);
        } else {
            const float*  c_s = (kc & 1) ? cb1 : cb0;
            const float2* qd  = (kc & 1) ? qb1 : qb0;
            #pragma unroll 2
            for (int k = 0; k < 64; k++) {
                const float4* qp = (const float4*)(qd + k * 32 + hg * 8);
                float4 q0 = qp[0], q1 = qp[1], q2 = qp[2], q3 = qp[3];
                float2 c2[4];
                #pragma unroll
                for (int j = 0; j < 4; j++)
                    c2[j] = *(const float2*)&c_s[k * 258 + sg * 2 + j * 64];
                #pragma unroll
                for (int j = 0; j < 4; j++) {
                    acc[0][j] = ffma2(make_float2(q0.x, q0.y), c2[j], acc[0][j]);
                    acc[1][j] = ffma2(make_float2(q0.z, q0.w), c2[j], acc[1][j]);
                    acc[2][j] = ffma2(make_float2(q1.x, q1.y), c2[j], acc[2][j]);
                    acc[3][j] = ffma2(make_float2(q1.z, q1.w), c2[j], acc[3][j]);
                    acc[4][j] = ffma2(make_float2(q2.x, q2.y), c2[j], acc[4][j]);
                    acc[5][j] = ffma2(make_float2(q2.z, q2.w), c2[j], acc[5][j]);
                    acc[6][j] = ffma2(make_float2(q3.x, q3.y), c2[j], acc[6][j]);
                    acc[7][j] = ffma2(make_float2(q3.z, q3.w), c2[j], acc[7][j]);
                }
            }
        }
        __syncthreads();
    }
    if (!prod) {
        #pragma unroll
        for (int i = 0; i < 8; i++)
            #pragma unroll
            for (int j = 0; j < 4; j++)
                *(float2*)&g_scores[((size_t)b * HH + hg * 8 + i) * TOTALN
                                    + s0 + sg * 2 + j * 64] = acc[i][j];
    }
}

// ---------------- K4: softmax over 8192 per (b,h) ----------------
__global__ __launch_bounds__(256) void k_softmax() {
    int bh = blockIdx.x;
    int tid = threadIdx.x;
    int w = tid >> 5, lane = tid & 31;
    float* row = g_scores + (size_t)bh * TOTALN;
    float4 v[8];
    #pragma unroll
    for (int i = 0; i < 8; i++) v[i] = ((float4*)row)[tid * 8 + i];
    float m = -1e30f;
    #pragma unroll
    for (int i = 0; i < 8; i++)
        m = fmaxf(m, fmaxf(fmaxf(v[i].x, v[i].y), fmaxf(v[i].z, v[i].w)));
    #pragma unroll
    for (int o = 16; o; o >>= 1) m = fmaxf(m, __shfl_xor_sync(0xffffffffu, m, o));
    __shared__ float redm[8], reds[8];
    if (lane == 0) redm[w] = m;
    __syncthreads();
    m = redm[0];
    #pragma unroll
    for (int i = 1; i < 8; i++) m = fmaxf(m, redm[i]);
    float s = 0.f;
    #pragma unroll
    for (int i = 0; i < 8; i++) {
        v[i].x = __expf(v[i].x - m); v[i].y = __expf(v[i].y - m);
        v[i].z = __expf(v[i].z - m); v[i].w = __expf(v[i].w - m);
        s += v[i].x + v[i].y + v[i].z + v[i].w;
    }
    #pragma unroll
    for (int o = 16; o; o >>= 1) s += __shfl_xor_sync(0xffffffffu, s, o);
    if (lane == 0) reds[w] = s;
    __syncthreads();
    s = reds[0] + reds[1] + reds[2] + reds[3] + reds[4] + reds[5] + reds[6] + reds[7];
    float inv = 1.f / s;
    #pragma unroll
    for (int i = 0; i < 8; i++) {
        v[i].x *= inv; v[i].y *= inv; v[i].z *= inv; v[i].w *= inv;
        ((float4*)row)[tid * 8 + i] = v[i];
    }
}

// ---------------- K5: o_c partials = attn @ c_full — cp.async double-buffered ----------------
// grid (sc=16, b=8); 256 threads; 16 chunks of 32 s
__device__ __forceinline__ void ov_issue(unsigned sb, const float* __restrict__ past_c,
                                         int b, int s0, int bufbase, int tid) {
    #pragma unroll
    for (int t = 0; t < 16; t++) {
        int i = tid + t * 256;
        int s = i >> 7, n4 = i & 127;
        const float* row = (s0 + s < PASTN) ? past_c + ((size_t)b * PASTN + s0 + s) * KVV
                                            : g_cnew + b * KVV;
        cp_async16(sb + (unsigned)(bufbase + s * 512 + n4 * 4) * 4u, row + n4 * 4);
    }
    cp_commit();
}

__global__ __launch_bounds__(256) void k_ov(const float* __restrict__ past_c) {
    extern __shared__ float sm[];
    float*  cb = sm;                          // 2 * 16384 floats (128KB)
    float2* ad = (float2*)(sm + 2 * 16384);   // 1024 float2 (8KB)
    int sc = blockIdx.x, b = blockIdx.y;
    int tid = threadIdx.x;
    unsigned sb;
    asm("{.reg .u64 t; cvta.to.shared.u64 t, %1; cvt.u32.u64 %0, t;}" : "=r"(sb) : "l"(sm));
    int S0 = sc * 512;
    int hg = tid >> 6, ng = tid & 63;
    float2 acc[8][4];
    #pragma unroll
    for (int i = 0; i < 8; i++)
        #pragma unroll
        for (int j = 0; j < 4; j++) acc[i][j] = make_float2(0.f, 0.f);

    ov_issue(sb, past_c, b, S0, 0, tid);

    for (int ch = 0; ch < 16; ch++) {
        int s0 = S0 + ch * 32;
        if (ch < 15) ov_issue(sb, past_c, b, s0 + 32, ((ch + 1) & 1) * 16384, tid);
        if (ch < 15) asm volatile("cp.async.wait_group 1;");
        else         asm volatile("cp.async.wait_group 0;");
        __syncthreads();                       // prev compute done + tile visible
        #pragma unroll
        for (int t = 0; t < 4; t++) {
            int i = tid + t * 256;
            int s2 = i >> 5, hh = i & 31;
            float a = g_scores[((size_t)b * HH + hh) * TOTALN + s0 + s2];
            ad[s2 * 32 + hh] = make_float2(a, a);
        }
        __syncthreads();                       // ad ready
        const float* c_s = cb + (ch & 1) * 16384;
        #pragma unroll 2
        for (int s = 0; s < 32; s++) {
            const float4* ap4 = (const float4*)(ad + s * 32 + hg * 8);
            float4 a0 = ap4[0], a1 = ap4[1], a2 = ap4[2], a3 = ap4[3];
            float2 c2[4];
            #pragma unroll
            for (int j = 0; j < 4; j++)
                c2[j] = *(const float2*)&c_s[s * 512 + ng * 2 + j * 128];
            #pragma unroll
            for (int j = 0; j < 4; j++) {
                acc[0][j] = ffma2(make_float2(a0.x, a0.y), c2[j], acc[0][j]);
                acc[1][j] = ffma2(make_float2(a0.z, a0.w), c2[j], acc[1][j]);
                acc[2][j] = ffma2(make_float2(a1.x, a1.y), c2[j], acc[2][j]);
                acc[3][j] = ffma2(make_float2(a1.z, a1.w), c2[j], acc[3][j]);
                acc[4][j] = ffma2(make_float2(a2.x, a2.y), c2[j], acc[4][j]);
                acc[5][j] = ffma2(make_float2(a2.z, a2.w), c2[j], acc[5][j]);
                acc[6][j] = ffma2(make_float2(a3.x, a3.y), c2[j], acc[6][j]);
                acc[7][j] = ffma2(make_float2(a3.z, a3.w), c2[j], acc[7][j]);
            }
        }
    }
    #pragma unroll
    for (int i = 0; i < 8; i++)
        #pragma unroll
        for (int j = 0; j < 4; j++)
            *(float2*)&g_opart[(((size_t)sc * BB + b) * HH + hg * 8 + i) * KVV
                               + ng * 2 + j * 128] = acc[i][j];
}

// reduce 16 s-partials -> g_oc
__global__ void k_redo() {
    int i = blockIdx.x * 256 + threadIdx.x;
    const float4* p = (const float4*)g_opart;
    float4 s = make_float4(0.f, 0.f, 0.f, 0.f);
    #pragma unroll
    for (int c = 0; c < 16; c++) {
        float4 t = p[c * 32768 + i];
        s.x += t.x; s.y += t.y; s.z += t.z; s.w += t.w;
    }
    ((float4*)g_oc)[i] = s;
}

// ---------------- K6: per-head v-up (n-split, atomic) ----------------
__global__ __launch_bounds__(128) void k_vup(const float* __restrict__ wv) {
    __shared__ float2 od[128][8];   // [n_local][b] dup pairs
    int h = blockIdx.x, nc = blockIdx.y;
    int tid = threadIdx.x;
    int jp = tid & 63, g = tid >> 6;
    for (int i = tid; i < 1024; i += 128) {
        int n = i >> 3, b = i & 7;
        float v = g_oc[((size_t)b * HH + h) * KVV + nc * 128 + n];
        od[n][b] = make_float2(v, v);
    }
    __syncthreads();
    float2 acc[BB];
    #pragma unroll
    for (int b = 0; b < BB; b++) acc[b] = make_float2(0.f, 0.f);
    const float* wp = wv + (size_t)(nc * 128 + g * 64) * (HH * HDD) + h * HDD + jp * 2;
    #pragma unroll 8
    for (int n = 0; n < 64; n++) {
        float2 w2 = *(const float2*)(wp + (size_t)n * (HH * HDD));
        #pragma unroll
        for (int b = 0; b < BB; b++)
            acc[b] = ffma2(od[g * 64 + n][b], w2, acc[b]);
    }
    #pragma unroll
    for (int b = 0; b < BB; b++) {
        atomicAdd(&g_ohead[b * DD + h * HDD + jp * 2 + 0], acc[b].x);
        atomicAdd(&g_ohead[b * DD + h * HDD + jp * 2 + 1], acc[b].y);
    }
}

// ---------------- K7: out = out_head @ w_o (m-split over 16, atomic) ----------------
__global__ __launch_bounds__(128) void k_oproj(const float* __restrict__ wo,
                                               float* __restrict__ out) {
    __shared__ float2 ohd[256][8];   // [m_local][b] dup pairs
    int dt = blockIdx.x, mc = blockIdx.y;
    int tid = threadIdx.x;
    for (int i = tid; i < 2048; i += 128) {
        int m = i >> 3, b = i & 7;
        float v = g_ohead[b * DD + mc * 256 + m];
        ohd[m][b] = make_float2(v, v);
    }
    __syncthreads();
    float2 acc[BB];
    #pragma unroll
    for (int b = 0; b < BB; b++) acc[b] = make_float2(0.f, 0.f);
    const float* wp = wo + (size_t)mc * 256 * DD + dt * 256 + tid * 2;
    #pragma unroll 8
    for (int m = 0; m < 256; m++) {
        float2 w2 = *(const float2*)(wp + (size_t)m * DD);
        #pragma unroll
        for (int b = 0; b < BB; b++)
            acc[b] = ffma2(ohd[m][b], w2, acc[b]);
    }
    #pragma unroll
    for (int b = 0; b < BB; b++) {
        atomicAdd(&out[b * DD + dt * 256 + tid * 2 + 0], acc[b].x);
        atomicAdd(&out[b * DD + dt * 256 + tid * 2 + 1], acc[b].y);
    }
}

// ---------------- launch ----------------
extern "C" void kernel_launch(void* const* d_in, const int* in_sizes, int n_in,
                              void* d_out, int out_size) {
    const float* x      = (const float*)d_in[0];
    const float* past_c = (const float*)d_in[1];
    const float* aqk    = (const float*)d_in[2];
    const float* wc     = (const float*)d_in[3];
    const float* wv     = (const float*)d_in[4];
    const float* wo     = (const float*)d_in[5];
    float* out = (float*)d_out;

    const int SMEM_K3 = (2 * 16512 + 2 * 2048 * 2) * 4;   // 164864
    const int SMEM_K5 = (2 * 16384 + 1024 * 2) * 4;        // 139264
    cudaFuncSetAttribute(k_scores, cudaFuncAttributeMaxDynamicSharedMemorySize, SMEM_K3);
    cudaFuncSetAttribute(k_ov,     cudaFuncAttributeMaxDynamicSharedMemorySize, SMEM_K5);

    k_init<<<128, 256>>>(out);
    k_compress<<<32, 256>>>(x, wc);
    k_qabs<<<dim3(8, 32), 128>>>(x, aqk);
    k_redq<<<128, 256>>>();
    k_scores<<<dim3(32, 8), 256, SMEM_K3>>>(past_c);
    k_softmax<<<256, 256>>>();
    k_ov<<<dim3(16, 8), 256, SMEM_K5>>>(past_c);
    k_redo<<<128, 256>>>();
    k_vup<<<dim3(32, 4), 128>>>(wv);
    k_oproj<<<dim3(16, 16), 128>>>(wo, out);
}